// round 11
// baseline (speedup 1.0000x reference)
#include <cuda_runtime.h>
#include <cuda_bf16.h>
#include <math.h>
#include <stdint.h>

#define Bsz 2
#define Cch 64
#define Hh  256
#define Ww  1216
#define HWs (Hh*Ww)          // 311296
#define NS  20000
#define Kn  9
#define Dd  131
#define Dhh 65
#define ICP 16

// conv tile geometry: 8 rows x 32 cols, warp = row, M=32 per warp
#define TR 8
#define TC 32
#define HR (TR+2)            // 10
#define HC (TC+2)            // 34
#define NCELL (HR*HC)        // 340
#define A_BYTES (NCELL*ICP*2)        // 10880 per part
#define BUFB (2*A_BYTES + 36864)     // 58624

// packed activation tensor: [cc(4)][b(2)][HW][16ch] bf16
#define PKT ((size_t)4*Bsz*HWs*16)

// point-MLP tiling
#define NROW ((size_t)Bsz*NS*Kn)   // 360000
#define TPB  11250
#define NTILE (Bsz*TPB)            // 22500

// ---------------- scratch (device globals) ----------------
__device__ float g_d0[(size_t)Bsz*HWs*Cch];    // NHWC fp32
__device__ float g_r0[(size_t)Bsz*HWs*Cch];    // NHWC fp32
__device__ float g_dfeat[(size_t)Bsz*Cch*NS];
__device__ float g_rfeat[(size_t)Bsz*Cch*NS];
__device__ __nv_bfloat16 g_pk_h[4*PKT];        // 0 sdepth, 1 rgb, 2 d0', 3 r0'
__device__ __nv_bfloat16 g_pk_l[4*PKT];
#define WSET_U32 36864
__device__ uint32_t g_wfrag[6*WSET_U32];
__device__ uint32_t g_ffrag[(size_t)NTILE*9*32*8];
__device__ uint32_t g_mfrag[162*32*4];
__device__ float g_logd[NROW];
__device__ float g_logr[NROW];

// ---------------- helpers ----------------
#define CP16(dst, src, sz) \
    asm volatile("cp.async.cg.shared.global [%0], [%1], 16, %2;\n" \
                 :: "r"(dst), "l"(src), "r"(sz))
#define CPCOMMIT() asm volatile("cp.async.commit_group;\n")
#define CPWAIT(N)  asm volatile("cp.async.wait_group %0;\n" :: "n"(N))

__device__ __forceinline__ uint32_t pack_bf2(float a, float b) {
    __nv_bfloat162 t;
    t.x = __float2bfloat16(a);
    t.y = __float2bfloat16(b);
    return *reinterpret_cast<uint32_t*>(&t);
}

__device__ __forceinline__ void split2(float x, float y, uint32_t& hi, uint32_t& lo) {
    float hx = __bfloat162float(__float2bfloat16(x));
    float hy = __bfloat162float(__float2bfloat16(y));
    hi = pack_bf2(hx, hy);
    lo = pack_bf2(x - hx, y - hy);
}

__device__ __forceinline__ void mma_bf16(float c[4], const uint32_t a[4],
                                         uint32_t b0, uint32_t b1) {
    asm volatile(
        "mma.sync.aligned.m16n8k16.row.col.f32.bf16.bf16.f32 "
        "{%0,%1,%2,%3}, {%4,%5,%6,%7}, {%8,%9}, {%0,%1,%2,%3};"
        : "+f"(c[0]), "+f"(c[1]), "+f"(c[2]), "+f"(c[3])
        : "r"(a[0]), "r"(a[1]), "r"(a[2]), "r"(a[3]), "r"(b0), "r"(b1));
}

__device__ __forceinline__ void ldsm4(uint32_t a[4], uint32_t addr) {
    asm volatile("ldmatrix.sync.aligned.m8n8.x4.shared.b16 {%0,%1,%2,%3}, [%4];"
                 : "=r"(a[0]), "=r"(a[1]), "=r"(a[2]), "=r"(a[3]) : "r"(addr));
}

// ---------------- conv weight prepack ----------------
__global__ void prepack_w(const float* __restrict__ w0, const float* __restrict__ w1,
                          const float* __restrict__ w2, const float* __restrict__ w3,
                          const float* __restrict__ w4, const float* __restrict__ w5)
{
    const float* w;
    switch (blockIdx.y) {
        case 0: w = w0; break; case 1: w = w1; break; case 2: w = w2; break;
        case 3: w = w3; break; case 4: w = w4; break; default: w = w5; break;
    }
    uint32_t* dst = g_wfrag + blockIdx.y * WSET_U32;

    int cb = blockIdx.x;
    int chunk = cb / 72;
    int rem = cb % 72;
    int tap = rem / 8;
    int nf = rem % 8;
    int lane = threadIdx.x;

    int oc = nf*8 + (lane >> 2);
    int k0 = (lane & 3) * 2;
    int ic = chunk*16 + k0;

    float v00 = w[oc*576 + ic*9 + tap];
    float v01 = w[oc*576 + (ic+1)*9 + tap];
    float v10 = w[oc*576 + (ic+8)*9 + tap];
    float v11 = w[oc*576 + (ic+9)*9 + tap];

    size_t base = ((((size_t)chunk*9 + tap)*8 + nf)*32 + lane)*4;
    uint32_t h0, l0, h1, l1;
    split2(v00, v01, h0, l0);
    split2(v10, v11, h1, l1);
    dst[base + 0] = h0;
    dst[base + 1] = h1;
    dst[base + 2] = l0;
    dst[base + 3] = l1;
}

// ---------------- MLP weight prepack ----------------
__global__ void prepack_mlp(const float* __restrict__ dw1, const float* __restrict__ rw1)
{
    int cb = blockIdx.x;
    int chunk = cb / 18, nf = cb % 18;
    int lane = threadIdx.x;
    int jl = lane >> 2;
    int kq = 2*(lane & 3);
    const float* W;
    int j;
    if (nf < 9) { W = dw1; j = nf*8 + jl; }
    else        { W = rw1; j = (nf-9)*8 + jl; }
    bool jv = (j < Dhh);
    int k0 = chunk*16 + kq;
    float v0 = (jv && k0   < Dd) ? W[(k0  )*Dhh + j] : 0.f;
    float v1 = (jv && k0+1 < Dd) ? W[(k0+1)*Dhh + j] : 0.f;
    float v2 = (jv && k0+8 < Dd) ? W[(k0+8)*Dhh + j] : 0.f;
    float v3 = (jv && k0+9 < Dd) ? W[(k0+9)*Dhh + j] : 0.f;
    uint32_t h0, l0, h1, l1;
    split2(v0, v1, h0, l0);
    split2(v2, v3, h1, l1);
    *(uint4*)&g_mfrag[((size_t)cb*32 + lane)*4] = make_uint4(h0, h1, l0, l1);
}

// ---------------- source prepack: NCHW fp32 -> packed bf16 hi/lo -----------
__global__ __launch_bounds__(256) void prepack_src(
    const float* __restrict__ sdepth, const float* __restrict__ rgb)
{
    __shared__ float s[64][65];
    const int tid = threadIdx.x;
    const int hw0 = blockIdx.x * 64;
    const int set = blockIdx.y & 1;
    const int b   = blockIdx.y >> 1;
    const float* src = set ? rgb : sdepth;
    __nv_bfloat16* dsth = g_pk_h + (size_t)set*PKT;
    __nv_bfloat16* dstl = g_pk_l + (size_t)set*PKT;

    for (int i = tid; i < 64*64; i += 256) {
        int c = i >> 6, p = i & 63;
        s[c][p] = src[((size_t)b*64 + c)*HWs + hw0 + p];
    }
    __syncthreads();

    for (int i = tid; i < 512; i += 256) {
        int p   = i >> 3;
        int cc  = (i >> 1) & 3;
        int sub = i & 1;
        uint32_t ph[4], pl[4];
#pragma unroll
        for (int j = 0; j < 4; j++)
            split2(s[cc*16 + sub*8 + 2*j][p], s[cc*16 + sub*8 + 2*j+1][p], ph[j], pl[j]);
        size_t o = (((size_t)cc*Bsz + b)*HWs + hw0 + p)*16 + sub*8;
        *(uint4*)&dsth[o] = make_uint4(ph[0], ph[1], ph[2], ph[3]);
        *(uint4*)&dstl[o] = make_uint4(pl[0], pl[1], pl[2], pl[3]);
    }
}

// ---------------- conv 3x3 SAME via mma, Mw=2 (warp M=32) ------------------
// grid (Ww/TC, Hh/TR, 2*Bsz): z&1 = set (d/r), z>>1 = b.
// mode 0: stage A -> NHWC fp32 + packed bf16 tensors 2/3.
// mode 1: stage C (2 sources) -> NCHW fp32 to outp.
__global__ __launch_bounds__(256, 2) void conv3x3_mma(
    const float* __restrict__ bd0, const float* __restrict__ br0,
    const float* __restrict__ bd2, const float* __restrict__ bd1,
    const float* __restrict__ br2, const float* __restrict__ br1,
    float* __restrict__ outp, int mode)
{
    extern __shared__ __align__(16) unsigned char sraw[];

    const int tid  = threadIdx.x;
    const int lane = tid & 31;
    const int wid  = tid >> 5;
    const int w0c  = blockIdx.x * TC;
    const int h0   = blockIdx.y * TR;
    const int set  = blockIdx.z & 1;
    const int b    = blockIdx.z >> 1;

    float c[2][8][4];
#pragma unroll
    for (int mf = 0; mf < 2; mf++)
#pragma unroll
        for (int nf = 0; nf < 8; nf++)
#pragma unroll
            for (int j = 0; j < 4; j++) c[mf][nf][j] = 0.f;

    const int mm   = lane & 15;
    const int kofs = (lane >> 4) << 3;
    const int n_chunks = mode ? 8 : 4;

    uint32_t s_ah = (uint32_t)__cvta_generic_to_shared(sraw);
    uint32_t s_al = s_ah + A_BYTES;
    uint32_t s_bfa = s_ah + 2*A_BYTES;
    const uint32_t* s_bf = (const uint32_t*)(sraw + 2*A_BYTES);

#pragma unroll 1
    for (int icc = 0; icc < n_chunks; icc++) {
        // ---- fill (cp.async) ----
        {
            int srcsel = icc >> 2, cc = icc & 3;
            int t, wset;
            if (mode == 0)       { t = set;     wset = set; }
            else if (srcsel == 0){ t = 2 + set; wset = 2 + 2*set; }
            else                 { t = set;     wset = 3 + 2*set; }
            const __nv_bfloat16* bh = g_pk_h + (size_t)t*PKT + ((size_t)cc*Bsz + b)*HWs*16;
            const __nv_bfloat16* bl = g_pk_l + (size_t)t*PKT + ((size_t)cc*Bsz + b)*HWs*16;
            for (int j = tid; j < NCELL*4; j += 256) {
                int cell = j >> 2, q = j & 3;
                int r = cell / HC, cl = cell - r*HC;
                int h = h0 - 1 + r, w = w0c - 1 + cl;
                bool ok = ((unsigned)h < (unsigned)Hh) && ((unsigned)w < (unsigned)Ww);
                const __nv_bfloat16* sp = ((q & 2) ? bl : bh)
                    + (ok ? (((size_t)h*Ww + w)*16 + (size_t)((q & 1)*8)) : 0);
                uint32_t dp = ((q & 2) ? s_al : s_ah) + cell*32 + (q & 1)*16;
                CP16(dp, sp, ok ? 16 : 0);
            }
            const uint4* wsrc = (const uint4*)(g_wfrag + (size_t)wset*WSET_U32 + (size_t)cc*9216);
            for (int i = tid; i < 2304; i += 256)
                CP16(s_bfa + i*16, wsrc + i, 16);
        }
        CPCOMMIT();
        CPWAIT(0);
        __syncthreads();

        // ---- compute: 9 taps, 2 m-frags share B regs ----
#pragma unroll 1
        for (int tap = 0; tap < 9; tap++) {
            const int dy = tap / 3, dx = tap % 3;
            uint32_t ai0 = (uint32_t)((((wid + dy)*HC) + (mm + dx))*ICP + kofs) * 2u;
            uint32_t ai1 = ai0 + (uint32_t)(16*ICP*2);
            uint32_t ah0[4], al0[4], ah1[4], al1[4];
            ldsm4(ah0, s_ah + ai0);
            ldsm4(al0, s_al + ai0);
            ldsm4(ah1, s_ah + ai1);
            ldsm4(al1, s_al + ai1);
#pragma unroll
            for (int nf = 0; nf < 8; nf++) {
                uint4 bb = *(const uint4*)&s_bf[((tap*8 + nf)*32 + lane)*4];
                mma_bf16(c[0][nf], ah0, bb.x, bb.y);
                mma_bf16(c[1][nf], ah1, bb.x, bb.y);
                mma_bf16(c[0][nf], ah0, bb.z, bb.w);
                mma_bf16(c[1][nf], ah1, bb.z, bb.w);
                mma_bf16(c[0][nf], al0, bb.x, bb.y);
                mma_bf16(c[1][nf], al1, bb.x, bb.y);
            }
        }
        __syncthreads();
    }

    if (!mode) {
        // NHWC fp32 + packed bf16 (tensors 2/3) epilogue
        float* y = set ? g_r0 : g_d0;
        const float* B = set ? br0 : bd0;
        __nv_bfloat16* th = g_pk_h + (size_t)(2 + set)*PKT;
        __nv_bfloat16* tl = g_pk_l + (size_t)(2 + set)*PKT;
        int col0 = lane >> 2;
        int ocq  = (lane & 3)*2;
#pragma unroll
        for (int mf = 0; mf < 2; mf++) {
            size_t hwb = (size_t)(h0 + wid)*Ww + w0c + mf*16 + col0;
#pragma unroll
            for (int nf = 0; nf < 8; nf++) {
                int oc = nf*8 + ocq;
                float bb0 = B[oc], bb1 = B[oc+1];
                float v00 = fmaxf(c[mf][nf][0] + bb0, 0.f);
                float v01 = fmaxf(c[mf][nf][1] + bb1, 0.f);
                float v10 = fmaxf(c[mf][nf][2] + bb0, 0.f);
                float v11 = fmaxf(c[mf][nf][3] + bb1, 0.f);
                float2 p0 = {v00, v01}, p1 = {v10, v11};
                *(float2*)&y[((size_t)b*HWs + hwb)*64 + oc]       = p0;
                *(float2*)&y[((size_t)b*HWs + hwb + 8)*64 + oc]   = p1;
                int cc = nf >> 1;
                int co = (nf & 1)*8 + ocq;
                size_t o0 = (((size_t)cc*Bsz + b)*HWs + hwb)*16 + co;
                uint32_t hh, ll;
                split2(v00, v01, hh, ll);
                *(uint32_t*)&th[o0] = hh;
                *(uint32_t*)&tl[o0] = ll;
                split2(v10, v11, hh, ll);
                *(uint32_t*)&th[o0 + 8*16] = hh;
                *(uint32_t*)&tl[o0 + 8*16] = ll;
            }
        }
    } else {
        // NCHW fp32 epilogue via smem transpose, two 128-px passes
        float* s_out = (float*)sraw;
        float* y = outp + (size_t)set*Bsz*Cch*HWs;
#pragma unroll 1
        for (int mf = 0; mf < 2; mf++) {
            __syncthreads();
            {
                int pix0 = wid*16 + (lane >> 2);
                int oc0  = (lane & 3) * 2;
#pragma unroll
                for (int nf = 0; nf < 8; nf++) {
                    int oc = nf*8 + oc0;
                    s_out[pix0*66 + oc]         = c[mf][nf][0];
                    s_out[pix0*66 + oc + 1]     = c[mf][nf][1];
                    s_out[(pix0+8)*66 + oc]     = c[mf][nf][2];
                    s_out[(pix0+8)*66 + oc + 1] = c[mf][nf][3];
                }
            }
            __syncthreads();
            for (int i = tid; i < 8192; i += 256) {
                int oc = i >> 7;
                int pix = i & 127;
                float bias = set ? (br2[oc] + br1[oc]) : (bd2[oc] + bd1[oc]);
                float v = s_out[pix*66 + oc] + bias;
                v = fmaxf(v, 0.f);
                y[((size_t)(b*Cch + oc))*HWs + (size_t)(h0 + (pix >> 4))*Ww
                  + (w0c + mf*16 + (pix & 15))] = v;
            }
        }
    }
}

// ---------------- P1: build feature A-fragments ----------------
__global__ __launch_bounds__(256) void build_feat(
    const int* __restrict__ pc, const int* __restrict__ nbrs,
    const float* __restrict__ disp)
{
    int gw = (blockIdx.x*256 + threadIdx.x) >> 5;
    if (gw >= NTILE) return;
    int lane = threadIdx.x & 31;
    int b = gw / TPB;
    int row0 = (gw - b*TPB) * 16;
    int q = lane & 3;
    int r1 = lane >> 2;
    int rw1 = row0 + r1, rw2 = rw1 + 8;
    int n1 = rw1/9, k1 = rw1 - n1*9;
    int n2 = rw2/9, k2 = rw2 - n2*9;
    int nb1 = nbrs[((size_t)b*NS + n1)*Kn + k1];
    int nb2 = nbrs[((size_t)b*NS + n2)*Kn + k2];
    int p1 = pc[(size_t)b*NS + n1];
    int p2 = pc[(size_t)b*NS + n2];
    const float* d0b = g_d0 + (size_t)b*HWs*64;
    const float* r0b = g_r0 + (size_t)b*HWs*64;
    uint32_t* dst0 = g_ffrag + (((size_t)gw*9)*32 + lane)*8;

#pragma unroll
    for (int dc = 0; dc < 4; dc++) {
        int cA = dc*16 + 2*q, cB = cA + 8;
        float2 nA1 = *(const float2*)&d0b[(size_t)nb1*64 + cA];
        float2 nB1 = *(const float2*)&d0b[(size_t)nb1*64 + cB];
        float2 nA2 = *(const float2*)&d0b[(size_t)nb2*64 + cA];
        float2 nB2 = *(const float2*)&d0b[(size_t)nb2*64 + cB];
        float2 dA1 = *(const float2*)&d0b[(size_t)p1*64 + cA];
        float2 dB1 = *(const float2*)&d0b[(size_t)p1*64 + cB];
        float2 dA2 = *(const float2*)&d0b[(size_t)p2*64 + cA];
        float2 dB2 = *(const float2*)&d0b[(size_t)p2*64 + cB];
        float2 rA1 = *(const float2*)&r0b[(size_t)p1*64 + cA];
        float2 rB1 = *(const float2*)&r0b[(size_t)p1*64 + cB];
        float2 rA2 = *(const float2*)&r0b[(size_t)p2*64 + cA];
        float2 rB2 = *(const float2*)&r0b[(size_t)p2*64 + cB];

        uint32_t h0,h1,h2,h3,l0,l1,l2,l3;
        split2(nA1.x - dA1.x, nA1.y - dA1.y, h0, l0);
        split2(nA2.x - dA2.x, nA2.y - dA2.y, h1, l1);
        split2(nB1.x - dB1.x, nB1.y - dB1.y, h2, l2);
        split2(nB2.x - dB2.x, nB2.y - dB2.y, h3, l3);
        uint32_t* d1 = dst0 + (size_t)dc*32*8;
        *(uint4*)(d1)     = make_uint4(h0, h1, h2, h3);
        *(uint4*)(d1 + 4) = make_uint4(l0, l1, l2, l3);
        split2(nA1.x - rA1.x, nA1.y - rA1.y, h0, l0);
        split2(nA2.x - rA2.x, nA2.y - rA2.y, h1, l1);
        split2(nB1.x - rB1.x, nB1.y - rB1.y, h2, l2);
        split2(nB2.x - rB2.x, nB2.y - rB2.y, h3, l3);
        uint32_t* d2 = dst0 + (size_t)(dc+4)*32*8;
        *(uint4*)(d2)     = make_uint4(h0, h1, h2, h3);
        *(uint4*)(d2 + 4) = make_uint4(l0, l1, l2, l3);
    }
    {
        float v0a = 0.f, v0b = 0.f, v1a = 0.f, v1b = 0.f;
        if (q == 0) {
            v0a = disp[(((size_t)b*3+0)*NS + n1)*Kn + k1];
            v0b = disp[(((size_t)b*3+1)*NS + n1)*Kn + k1];
            v1a = disp[(((size_t)b*3+0)*NS + n2)*Kn + k2];
            v1b = disp[(((size_t)b*3+1)*NS + n2)*Kn + k2];
        } else if (q == 1) {
            v0a = disp[(((size_t)b*3+2)*NS + n1)*Kn + k1];
            v1a = disp[(((size_t)b*3+2)*NS + n2)*Kn + k2];
        }
        uint32_t h0,h1,l0,l1;
        split2(v0a, v0b, h0, l0);
        split2(v1a, v1b, h1, l1);
        uint32_t* d8 = dst0 + (size_t)8*32*8;
        *(uint4*)(d8)     = make_uint4(h0, h1, 0u, 0u);
        *(uint4*)(d8 + 4) = make_uint4(l0, l1, 0u, 0u);
    }
}

// ---------------- P2: fused dual-MLP GEMM -> logits ----------------
__global__ __launch_bounds__(256) void mlp_gemm(
    const float* __restrict__ db1, const float* __restrict__ rb1,
    const float* __restrict__ dw2, const float* __restrict__ rw2)
{
    extern __shared__ uint32_t s_b[];
    const int tid  = threadIdx.x;
    const int lane = tid & 31;
    const int w    = tid >> 5;

    {
        const uint4* src = (const uint4*)g_mfrag;
        uint4* dst = (uint4*)s_b;
        for (int i = tid; i < 5184; i += 256) dst[i] = src[i];
    }
    __syncthreads();

    int t = blockIdx.x*8 + w;
    if (t >= NTILE) return;

    float c[18][4];
#pragma unroll
    for (int nf = 0; nf < 18; nf++)
#pragma unroll
        for (int j = 0; j < 4; j++) c[nf][j] = 0.f;

    const uint4* af = (const uint4*)g_ffrag;
#pragma unroll 1
    for (int chunk = 0; chunk < 9; chunk++) {
        size_t ai = (((size_t)t*9 + chunk)*32 + lane)*2;
        uint4 ahv = af[ai];
        uint4 alv = af[ai + 1];
        uint32_t ah[4] = {ahv.x, ahv.y, ahv.z, ahv.w};
        uint32_t al[4] = {alv.x, alv.y, alv.z, alv.w};
#pragma unroll
        for (int nf = 0; nf < 18; nf++) {
            uint4 bb = *(const uint4*)&s_b[((chunk*18 + nf)*32 + lane)*4];
            mma_bf16(c[nf], ah, bb.x, bb.y);
            mma_bf16(c[nf], ah, bb.z, bb.w);
            mma_bf16(c[nf], al, bb.x, bb.y);
        }
    }

    float sd1 = 0.f, sd2 = 0.f, sr1 = 0.f, sr2 = 0.f;
    int ocq = (lane & 3)*2;
#pragma unroll
    for (int nf = 0; nf < 18; nf++) {
        int jj = (nf < 9) ? (nf*8 + ocq) : ((nf-9)*8 + ocq);
        const float* B1 = (nf < 9) ? db1 : rb1;
        const float* W2 = (nf < 9) ? dw2 : rw2;
        float bb0 = (jj   < Dhh) ? B1[jj]   : 0.f;
        float bb1 = (jj+1 < Dhh) ? B1[jj+1] : 0.f;
        float w20 = (jj   < Dhh) ? W2[jj]   : 0.f;
        float w21 = (jj+1 < Dhh) ? W2[jj+1] : 0.f;
        float h0 = c[nf][0] + bb0; h0 = (h0 > 0.f) ? h0 : 0.2f*h0;
        float h1 = c[nf][1] + bb1; h1 = (h1 > 0.f) ? h1 : 0.2f*h1;
        float h2 = c[nf][2] + bb0; h2 = (h2 > 0.f) ? h2 : 0.2f*h2;
        float h3 = c[nf][3] + bb1; h3 = (h3 > 0.f) ? h3 : 0.2f*h3;
        float s1 = h0*w20 + h1*w21;
        float s2 = h2*w20 + h3*w21;
        if (nf < 9) { sd1 += s1; sd2 += s2; }
        else        { sr1 += s1; sr2 += s2; }
    }
#pragma unroll
    for (int d = 1; d <= 2; d <<= 1) {
        sd1 += __shfl_xor_sync(0xffffffffu, sd1, d);
        sd2 += __shfl_xor_sync(0xffffffffu, sd2, d);
        sr1 += __shfl_xor_sync(0xffffffffu, sr1, d);
        sr2 += __shfl_xor_sync(0xffffffffu, sr2, d);
    }
    if ((lane & 3) == 0) {
        size_t row = (size_t)t*16 + (lane >> 2);
        g_logd[row]     = sd1;
        g_logd[row + 8] = sd2;
        g_logr[row]     = sr1;
        g_logr[row + 8] = sr2;
    }
}

// ---------------- P3: softmax + weighted neighbor sum ----------------
__global__ __launch_bounds__(64) void point_softmax(
    const int* __restrict__ nbrs,
    const float* __restrict__ d_bias, const float* __restrict__ r_bias)
{
    const int n = blockIdx.x;
    const int b = blockIdx.y;
    const int tid = threadIdx.x;
    __shared__ int s_nb[9];
    if (tid < Kn) s_nb[tid] = nbrs[((size_t)b*NS + n)*Kn + tid];
    __syncthreads();

    size_t base = ((size_t)b*NS + n)*Kn;
    float ld[9], lr[9];
    float mxd = -1e30f, mxr = -1e30f;
#pragma unroll
    for (int k = 0; k < Kn; k++) {
        ld[k] = g_logd[base + k];
        lr[k] = g_logr[base + k];
        mxd = fmaxf(mxd, ld[k]);
        mxr = fmaxf(mxr, lr[k]);
    }
    float sd = 0.f, sr = 0.f;
#pragma unroll
    for (int k = 0; k < Kn; k++) {
        ld[k] = expf(ld[k] - mxd); sd += ld[k];
        lr[k] = expf(lr[k] - mxr); sr += lr[k];
    }
    float invd = 1.f/sd, invr = 1.f/sr;
#pragma unroll
    for (int k = 0; k < Kn; k++) { ld[k] *= invd; lr[k] *= invr; }

    const float* d0b = g_d0 + (size_t)b*HWs*64;
    int ch = tid;
    float ad = d_bias[ch], ar = r_bias[ch];
#pragma unroll
    for (int k = 0; k < Kn; k++) {
        float dn = d0b[(size_t)s_nb[k]*64 + ch];
        ad = fmaf(ld[k], dn, ad);
        ar = fmaf(lr[k], dn, ar);
    }
    g_dfeat[((size_t)b*Cch + ch)*NS + n] = ad;
    g_rfeat[((size_t)b*Cch + ch)*NS + n] = ar;
}

// ---------------- scatter: update NHWC fp32 AND packed tensors 2/3 --------
__global__ __launch_bounds__(128) void scatter_kernel(const int* __restrict__ pc)
{
    const int n = blockIdx.x;
    const int b = blockIdx.y;
    const int tid = threadIdx.x;
    const int idx = pc[(size_t)b*NS + n];
    __shared__ float sd[64], sr[64];

    if (tid < 64) {
        int ch = tid;
        float v = g_dfeat[((size_t)b*Cch + ch)*NS + n];
        size_t o = ((size_t)b*HWs + idx)*64 + ch;
        float nv = (ch == 0) ? v : (g_d0[o] + v);
        g_d0[o] = nv;
        sd[ch] = nv;
    } else {
        int ch = tid - 64;
        float v = g_rfeat[((size_t)b*Cch + ch)*NS + n];
        size_t o = ((size_t)b*HWs + idx)*64 + ch;
        float nv = (ch == 0) ? v : (g_r0[o] + v);
        g_r0[o] = nv;
        sr[ch] = nv;
    }
    __syncthreads();

    // repack updated pixel into tensors 2 (d) / 3 (r)
    int set  = tid >> 6;
    int q    = tid & 63;
    int pr   = q >> 1;        // pair 0..31
    int part = q & 1;         // 0 = hi, 1 = lo
    int ch   = 2*pr;
    const float* s = set ? sr : sd;
    uint32_t hh, ll;
    split2(s[ch], s[ch+1], hh, ll);
    int cc = ch >> 4;
    size_t off = (((size_t)cc*Bsz + b)*HWs + idx)*16 + (ch & 15);
    if (part == 0)
        *(uint32_t*)&g_pk_h[(size_t)(2+set)*PKT + off] = hh;
    else
        *(uint32_t*)&g_pk_l[(size_t)(2+set)*PKT + off] = ll;
}

// ---------------------------------------------------------------------------
extern "C" void kernel_launch(void* const* d_in, const int* in_sizes, int n_in,
                              void* d_out, int out_size)
{
    const float* rgb    = (const float*)d_in[0];
    const float* sdepth = (const float*)d_in[1];
    const int*   pc     = (const int*)  d_in[2];
    const int*   nbrs   = (const int*)  d_in[3];
    const float* disp   = (const float*)d_in[4];
    const float* d_c0w  = (const float*)d_in[5];
    const float* d_c0b  = (const float*)d_in[6];
    const float* d_c1w  = (const float*)d_in[7];
    const float* d_c1b  = (const float*)d_in[8];
    const float* d_c2w  = (const float*)d_in[9];
    const float* d_c2b  = (const float*)d_in[10];
    const float* r_c0w  = (const float*)d_in[11];
    const float* r_c0b  = (const float*)d_in[12];
    const float* r_c1w  = (const float*)d_in[13];
    const float* r_c1b  = (const float*)d_in[14];
    const float* r_c2w  = (const float*)d_in[15];
    const float* r_c2b  = (const float*)d_in[16];
    const float* d_w1   = (const float*)d_in[17];
    const float* d_b1   = (const float*)d_in[18];
    const float* d_w2   = (const float*)d_in[19];
    const float* d_b2   = (const float*)d_in[20];
    const float* r_w1   = (const float*)d_in[21];
    const float* r_b1   = (const float*)d_in[22];
    const float* r_w2   = (const float*)d_in[23];
    const float* r_b2   = (const float*)d_in[24];
    const float* d_bias = (const float*)d_in[25];
    const float* r_bias = (const float*)d_in[26];
    float* out = (float*)d_out;
    (void)d_b2; (void)r_b2;   // softmax is shift-invariant

    cudaFuncSetAttribute(conv3x3_mma,
                         cudaFuncAttributeMaxDynamicSharedMemorySize, BUFB);
    cudaFuncSetAttribute(mlp_gemm,
                         cudaFuncAttributeMaxDynamicSharedMemorySize, 82944);

    // weight prepacks: conv sets 0:d0 1:r0 2:d2 3:d1 4:r2 5:r1
    prepack_w<<<dim3(288, 6), 32>>>(d_c0w, r_c0w, d_c2w, d_c1w, r_c2w, r_c1w);
    prepack_mlp<<<162, 32>>>(d_w1, r_w1);
    prepack_src<<<dim3(HWs/64, 2*Bsz), 256>>>(sdepth, rgb);

    dim3 cgrid(Ww/TC, Hh/TR, 2*Bsz);

    // Stage A (both tensors, both batches) -> NHWC fp32 + packed tensors 2/3
    conv3x3_mma<<<cgrid, 256, BUFB>>>(d_c0b, r_c0b,
                                      nullptr, nullptr, nullptr, nullptr,
                                      nullptr, 0);

    // Stage B: tensorized point MLP
    build_feat<<<(NTILE*32 + 255)/256, 256>>>(pc, nbrs, disp);
    mlp_gemm<<<(NTILE + 7)/8, 256, 82944>>>(d_b1, r_b1, d_w2, r_w2);
    point_softmax<<<dim3(NS, Bsz), 64>>>(nbrs, d_bias, r_bias);
    scatter_kernel<<<dim3(NS, Bsz), 128>>>(pc);

    // Stage C (fused dual-source, both tensors) -> NCHW out
    conv3x3_mma<<<cgrid, 256, BUFB>>>(nullptr, nullptr,
                                      d_c2b, d_c1b, r_c2b, r_c1b,
                                      out, 1);
}

// round 12
// speedup vs baseline: 2.0793x; 2.0793x over previous
#include <cuda_runtime.h>
#include <cuda_bf16.h>
#include <math.h>
#include <stdint.h>

#define Bsz 2
#define Cch 64
#define Hh  256
#define Ww  1216
#define HWs (Hh*Ww)          // 311296
#define NS  20000
#define Kn  9
#define Dd  131
#define Dhh 65
#define ICP 16

// conv tile geometry (R10 proven: warp M=16, 8 rows x 16 cols)
#define TR 8
#define TC 16
#define HR (TR+2)            // 10
#define HC (TC+2)            // 18
#define NCELL (HR*HC)        // 180

// per-stage smem buffer: ah 5760 + al 5760 + B 36864 = 48384
#define BUFB 48384
#define SMEM_CONV (2*BUFB)   // 96768

// packed activation tensor: [cc(4)][b(2)][HW][16ch] bf16
#define PKT ((size_t)4*Bsz*HWs*16)

// point-MLP tiling
#define NROW ((size_t)Bsz*NS*Kn)   // 360000
#define TPB  11250
#define NTILE (Bsz*TPB)            // 22500

// ---------------- scratch (device globals) ----------------
__device__ float g_d0[(size_t)Bsz*HWs*Cch];    // NHWC fp32
__device__ float g_r0[(size_t)Bsz*HWs*Cch];    // NHWC fp32
__device__ float g_dfeat[(size_t)Bsz*Cch*NS];
__device__ float g_rfeat[(size_t)Bsz*Cch*NS];
__device__ __nv_bfloat16 g_pk_h[4*PKT];        // 0 sdepth, 1 rgb, 2 d0', 3 r0'
__device__ __nv_bfloat16 g_pk_l[4*PKT];
#define WSET_U32 36864
__device__ uint32_t g_wfrag[6*WSET_U32];
__device__ uint32_t g_ffrag[(size_t)NTILE*9*32*8];
__device__ uint32_t g_mfrag[162*32*4];
__device__ float g_logd[NROW];
__device__ float g_logr[NROW];

// ---------------- helpers ----------------
#define CP16(dst, src, sz) \
    asm volatile("cp.async.cg.shared.global [%0], [%1], 16, %2;\n" \
                 :: "r"(dst), "l"(src), "r"(sz))
#define CPCOMMIT() asm volatile("cp.async.commit_group;\n")
#define CPWAIT(N)  asm volatile("cp.async.wait_group %0;\n" :: "n"(N))

__device__ __forceinline__ uint32_t pack_bf2(float a, float b) {
    __nv_bfloat162 t;
    t.x = __float2bfloat16(a);
    t.y = __float2bfloat16(b);
    return *reinterpret_cast<uint32_t*>(&t);
}

__device__ __forceinline__ void split2(float x, float y, uint32_t& hi, uint32_t& lo) {
    float hx = __bfloat162float(__float2bfloat16(x));
    float hy = __bfloat162float(__float2bfloat16(y));
    hi = pack_bf2(hx, hy);
    lo = pack_bf2(x - hx, y - hy);
}

__device__ __forceinline__ void mma_bf16(float c[4], const uint32_t a[4],
                                         uint32_t b0, uint32_t b1) {
    asm volatile(
        "mma.sync.aligned.m16n8k16.row.col.f32.bf16.bf16.f32 "
        "{%0,%1,%2,%3}, {%4,%5,%6,%7}, {%8,%9}, {%0,%1,%2,%3};"
        : "+f"(c[0]), "+f"(c[1]), "+f"(c[2]), "+f"(c[3])
        : "r"(a[0]), "r"(a[1]), "r"(a[2]), "r"(a[3]), "r"(b0), "r"(b1));
}

__device__ __forceinline__ void ldsm4(uint32_t a[4], uint32_t addr) {
    asm volatile("ldmatrix.sync.aligned.m8n8.x4.shared.b16 {%0,%1,%2,%3}, [%4];"
                 : "=r"(a[0]), "=r"(a[1]), "=r"(a[2]), "=r"(a[3]) : "r"(addr));
}

// ---------------- conv weight prepack ----------------
__global__ void prepack_w(const float* __restrict__ w0, const float* __restrict__ w1,
                          const float* __restrict__ w2, const float* __restrict__ w3,
                          const float* __restrict__ w4, const float* __restrict__ w5)
{
    const float* w;
    switch (blockIdx.y) {
        case 0: w = w0; break; case 1: w = w1; break; case 2: w = w2; break;
        case 3: w = w3; break; case 4: w = w4; break; default: w = w5; break;
    }
    uint32_t* dst = g_wfrag + blockIdx.y * WSET_U32;

    int cb = blockIdx.x;
    int chunk = cb / 72;
    int rem = cb % 72;
    int tap = rem / 8;
    int nf = rem % 8;
    int lane = threadIdx.x;

    int oc = nf*8 + (lane >> 2);
    int k0 = (lane & 3) * 2;
    int ic = chunk*16 + k0;

    float v00 = w[oc*576 + ic*9 + tap];
    float v01 = w[oc*576 + (ic+1)*9 + tap];
    float v10 = w[oc*576 + (ic+8)*9 + tap];
    float v11 = w[oc*576 + (ic+9)*9 + tap];

    size_t base = ((((size_t)chunk*9 + tap)*8 + nf)*32 + lane)*4;
    uint32_t h0, l0, h1, l1;
    split2(v00, v01, h0, l0);
    split2(v10, v11, h1, l1);
    dst[base + 0] = h0;
    dst[base + 1] = h1;
    dst[base + 2] = l0;
    dst[base + 3] = l1;
}

// ---------------- MLP weight prepack ----------------
__global__ void prepack_mlp(const float* __restrict__ dw1, const float* __restrict__ rw1)
{
    int cb = blockIdx.x;
    int chunk = cb / 18, nf = cb % 18;
    int lane = threadIdx.x;
    int jl = lane >> 2;
    int kq = 2*(lane & 3);
    const float* W;
    int j;
    if (nf < 9) { W = dw1; j = nf*8 + jl; }
    else        { W = rw1; j = (nf-9)*8 + jl; }
    bool jv = (j < Dhh);
    int k0 = chunk*16 + kq;
    float v0 = (jv && k0   < Dd) ? W[(k0  )*Dhh + j] : 0.f;
    float v1 = (jv && k0+1 < Dd) ? W[(k0+1)*Dhh + j] : 0.f;
    float v2 = (jv && k0+8 < Dd) ? W[(k0+8)*Dhh + j] : 0.f;
    float v3 = (jv && k0+9 < Dd) ? W[(k0+9)*Dhh + j] : 0.f;
    uint32_t h0, l0, h1, l1;
    split2(v0, v1, h0, l0);
    split2(v2, v3, h1, l1);
    *(uint4*)&g_mfrag[((size_t)cb*32 + lane)*4] = make_uint4(h0, h1, l0, l1);
}

// ---------------- source prepack: NCHW fp32 -> packed bf16 hi/lo -----------
__global__ __launch_bounds__(256) void prepack_src(
    const float* __restrict__ sdepth, const float* __restrict__ rgb)
{
    __shared__ float s[64][65];
    const int tid = threadIdx.x;
    const int hw0 = blockIdx.x * 64;
    const int set = blockIdx.y & 1;
    const int b   = blockIdx.y >> 1;
    const float* src = set ? rgb : sdepth;
    __nv_bfloat16* dsth = g_pk_h + (size_t)set*PKT;
    __nv_bfloat16* dstl = g_pk_l + (size_t)set*PKT;

    for (int i = tid; i < 64*64; i += 256) {
        int c = i >> 6, p = i & 63;
        s[c][p] = src[((size_t)b*64 + c)*HWs + hw0 + p];
    }
    __syncthreads();

    for (int i = tid; i < 512; i += 256) {
        int p   = i >> 3;
        int cc  = (i >> 1) & 3;
        int sub = i & 1;
        uint32_t ph[4], pl[4];
#pragma unroll
        for (int j = 0; j < 4; j++)
            split2(s[cc*16 + sub*8 + 2*j][p], s[cc*16 + sub*8 + 2*j+1][p], ph[j], pl[j]);
        size_t o = (((size_t)cc*Bsz + b)*HWs + hw0 + p)*16 + sub*8;
        *(uint4*)&dsth[o] = make_uint4(ph[0], ph[1], ph[2], ph[3]);
        *(uint4*)&dstl[o] = make_uint4(pl[0], pl[1], pl[2], pl[3]);
    }
}

// ---------------- conv 3x3 SAME via mma, cp.async double-buffered ----------
// grid (Ww/TC, Hh/TR, 2*Bsz): z&1 = set (d/r), z>>1 = b.
// mode 0: stage A -> NHWC fp32 g_d0/g_r0 + packed bf16 tensors 2/3.
// mode 1: stage C (2 sources) -> NCHW fp32 to outp (+set offset).
__global__ __launch_bounds__(256) void conv3x3_mma(
    const float* __restrict__ bd0, const float* __restrict__ br0,
    const float* __restrict__ bd2, const float* __restrict__ bd1,
    const float* __restrict__ br2, const float* __restrict__ br1,
    float* __restrict__ outp, int mode)
{
    extern __shared__ __align__(16) unsigned char sraw[];

    const int tid  = threadIdx.x;
    const int lane = tid & 31;
    const int wid  = tid >> 5;
    const int w0c  = blockIdx.x * TC;
    const int h0   = blockIdx.y * TR;
    const int set  = blockIdx.z & 1;
    const int b    = blockIdx.z >> 1;

    float c[8][4];
#pragma unroll
    for (int nf = 0; nf < 8; nf++)
#pragma unroll
        for (int j = 0; j < 4; j++) c[nf][j] = 0.f;

    const int mm   = lane & 15;
    const int kofs = (lane >> 4) << 3;
    const int n_chunks = mode ? 8 : 4;

    auto fill = [&](int icc, unsigned char* sb) {
        int srcsel = icc >> 2, cc = icc & 3;
        int t, wset;
        if (mode == 0)       { t = set;     wset = set; }
        else if (srcsel == 0){ t = 2 + set; wset = 2 + 2*set; }
        else                 { t = set;     wset = 3 + 2*set; }
        const __nv_bfloat16* bh = g_pk_h + (size_t)t*PKT + ((size_t)cc*Bsz + b)*HWs*16;
        const __nv_bfloat16* bl = g_pk_l + (size_t)t*PKT + ((size_t)cc*Bsz + b)*HWs*16;
        uint32_t s_ah = (uint32_t)__cvta_generic_to_shared(sb);
        uint32_t s_al = s_ah + 5760;
        uint32_t s_bf = s_ah + 11520;
        for (int j = tid; j < NCELL*4; j += 256) {
            int cell = j >> 2, q = j & 3;
            int r = cell / HC, cl = cell - r*HC;
            int h = h0 - 1 + r, w = w0c - 1 + cl;
            bool ok = ((unsigned)h < (unsigned)Hh) && ((unsigned)w < (unsigned)Ww);
            const __nv_bfloat16* sp = ((q & 2) ? bl : bh)
                + (ok ? (((size_t)h*Ww + w)*16 + (size_t)((q & 1)*8)) : 0);
            uint32_t dp = ((q & 2) ? s_al : s_ah) + cell*32 + (q & 1)*16;
            CP16(dp, sp, ok ? 16 : 0);
        }
        const uint4* wsrc = (const uint4*)(g_wfrag + (size_t)wset*WSET_U32 + (size_t)cc*9216);
        for (int i = tid; i < 2304; i += 256)
            CP16(s_bf + i*16, wsrc + i, 16);
    };

    fill(0, sraw);
    CPCOMMIT();

#pragma unroll 1
    for (int icc = 0; icc < n_chunks; icc++) {
        unsigned char* cur = sraw + (icc & 1)*BUFB;
        if (icc + 1 < n_chunks) {
            fill(icc + 1, sraw + ((icc + 1) & 1)*BUFB);
            CPCOMMIT();
            CPWAIT(1);
        } else {
            CPWAIT(0);
        }
        __syncthreads();

        uint32_t a_hi = (uint32_t)__cvta_generic_to_shared(cur);
        uint32_t a_lo = a_hi + 5760;
        const uint32_t* s_bf = (const uint32_t*)(cur + 11520);
#pragma unroll
        for (int tap = 0; tap < 9; tap++) {
            const int dy = tap / 3, dx = tap % 3;
            uint32_t aidx = (uint32_t)((((wid + dy)*HC) + (mm + dx))*ICP + kofs) * 2u;
            uint32_t ah[4], al[4];
            ldsm4(ah, a_hi + aidx);
            ldsm4(al, a_lo + aidx);
#pragma unroll
            for (int nf = 0; nf < 8; nf++) {
                uint4 bb = *(const uint4*)&s_bf[((tap*8 + nf)*32 + lane)*4];
                mma_bf16(c[nf], ah, bb.x, bb.y);
                mma_bf16(c[nf], ah, bb.z, bb.w);
                mma_bf16(c[nf], al, bb.x, bb.y);
            }
        }
        __syncthreads();
    }

    if (!mode) {
        // NHWC fp32 + packed bf16 (tensors 2/3) epilogue
        float* y = set ? g_r0 : g_d0;
        const float* B = set ? br0 : bd0;
        __nv_bfloat16* th = g_pk_h + (size_t)(2 + set)*PKT;
        __nv_bfloat16* tl = g_pk_l + (size_t)(2 + set)*PKT;
        int col0 = lane >> 2;
        int ocq  = (lane & 3)*2;
        size_t hwb = (size_t)(h0 + wid)*Ww + w0c + col0;
#pragma unroll
        for (int nf = 0; nf < 8; nf++) {
            int oc = nf*8 + ocq;
            float bb0 = B[oc], bb1 = B[oc+1];
            float v00 = fmaxf(c[nf][0] + bb0, 0.f);
            float v01 = fmaxf(c[nf][1] + bb1, 0.f);
            float v10 = fmaxf(c[nf][2] + bb0, 0.f);
            float v11 = fmaxf(c[nf][3] + bb1, 0.f);
            float2 p0 = {v00, v01}, p1 = {v10, v11};
            *(float2*)&y[((size_t)b*HWs + hwb)*64 + oc]     = p0;
            *(float2*)&y[((size_t)b*HWs + hwb + 8)*64 + oc] = p1;
            int cc = nf >> 1;
            int co = (nf & 1)*8 + ocq;
            size_t o0 = (((size_t)cc*Bsz + b)*HWs + hwb)*16 + co;
            uint32_t hh, ll;
            split2(v00, v01, hh, ll);
            *(uint32_t*)&th[o0] = hh;
            *(uint32_t*)&tl[o0] = ll;
            split2(v10, v11, hh, ll);
            *(uint32_t*)&th[o0 + 8*16] = hh;
            *(uint32_t*)&tl[o0 + 8*16] = ll;
        }
    } else {
        // NCHW fp32 epilogue via smem transpose
        float* s_out = (float*)sraw;
        float* y = outp + (size_t)set*Bsz*Cch*HWs;
        {
            int pix0 = wid*16 + (lane >> 2);
            int oc0  = (lane & 3) * 2;
#pragma unroll
            for (int nf = 0; nf < 8; nf++) {
                int oc = nf*8 + oc0;
                s_out[pix0*66 + oc]         = c[nf][0];
                s_out[pix0*66 + oc + 1]     = c[nf][1];
                s_out[(pix0+8)*66 + oc]     = c[nf][2];
                s_out[(pix0+8)*66 + oc + 1] = c[nf][3];
            }
        }
        __syncthreads();
        for (int i = tid; i < 8192; i += 256) {
            int oc = i >> 7;
            int pix = i & 127;
            float bias = set ? (br2[oc] + br1[oc]) : (bd2[oc] + bd1[oc]);
            float v = s_out[pix*66 + oc] + bias;
            v = fmaxf(v, 0.f);
            y[((size_t)(b*Cch + oc))*HWs + (size_t)(h0 + (pix >> 4))*Ww
              + (w0c + (pix & 15))] = v;
        }
    }
}

// ---------------- P1: build feature A-fragments ----------------
__global__ __launch_bounds__(256) void build_feat(
    const int* __restrict__ pc, const int* __restrict__ nbrs,
    const float* __restrict__ disp)
{
    int gw = (blockIdx.x*256 + threadIdx.x) >> 5;
    if (gw >= NTILE) return;
    int lane = threadIdx.x & 31;
    int b = gw / TPB;
    int row0 = (gw - b*TPB) * 16;
    int q = lane & 3;
    int r1 = lane >> 2;
    int rw1 = row0 + r1, rw2 = rw1 + 8;
    int n1 = rw1/9, k1 = rw1 - n1*9;
    int n2 = rw2/9, k2 = rw2 - n2*9;
    int nb1 = nbrs[((size_t)b*NS + n1)*Kn + k1];
    int nb2 = nbrs[((size_t)b*NS + n2)*Kn + k2];
    int p1 = pc[(size_t)b*NS + n1];
    int p2 = pc[(size_t)b*NS + n2];
    const float* d0b = g_d0 + (size_t)b*HWs*64;
    const float* r0b = g_r0 + (size_t)b*HWs*64;
    uint32_t* dst0 = g_ffrag + (((size_t)gw*9)*32 + lane)*8;

#pragma unroll
    for (int dc = 0; dc < 4; dc++) {
        int cA = dc*16 + 2*q, cB = cA + 8;
        float2 nA1 = *(const float2*)&d0b[(size_t)nb1*64 + cA];
        float2 nB1 = *(const float2*)&d0b[(size_t)nb1*64 + cB];
        float2 nA2 = *(const float2*)&d0b[(size_t)nb2*64 + cA];
        float2 nB2 = *(const float2*)&d0b[(size_t)nb2*64 + cB];
        float2 dA1 = *(const float2*)&d0b[(size_t)p1*64 + cA];
        float2 dB1 = *(const float2*)&d0b[(size_t)p1*64 + cB];
        float2 dA2 = *(const float2*)&d0b[(size_t)p2*64 + cA];
        float2 dB2 = *(const float2*)&d0b[(size_t)p2*64 + cB];
        float2 rA1 = *(const float2*)&r0b[(size_t)p1*64 + cA];
        float2 rB1 = *(const float2*)&r0b[(size_t)p1*64 + cB];
        float2 rA2 = *(const float2*)&r0b[(size_t)p2*64 + cA];
        float2 rB2 = *(const float2*)&r0b[(size_t)p2*64 + cB];

        uint32_t h0,h1,h2,h3,l0,l1,l2,l3;
        split2(nA1.x - dA1.x, nA1.y - dA1.y, h0, l0);
        split2(nA2.x - dA2.x, nA2.y - dA2.y, h1, l1);
        split2(nB1.x - dB1.x, nB1.y - dB1.y, h2, l2);
        split2(nB2.x - dB2.x, nB2.y - dB2.y, h3, l3);
        uint32_t* d1 = dst0 + (size_t)dc*32*8;
        *(uint4*)(d1)     = make_uint4(h0, h1, h2, h3);
        *(uint4*)(d1 + 4) = make_uint4(l0, l1, l2, l3);
        split2(nA1.x - rA1.x, nA1.y - rA1.y, h0, l0);
        split2(nA2.x - rA2.x, nA2.y - rA2.y, h1, l1);
        split2(nB1.x - rB1.x, nB1.y - rB1.y, h2, l2);
        split2(nB2.x - rB2.x, nB2.y - rB2.y, h3, l3);
        uint32_t* d2 = dst0 + (size_t)(dc+4)*32*8;
        *(uint4*)(d2)     = make_uint4(h0, h1, h2, h3);
        *(uint4*)(d2 + 4) = make_uint4(l0, l1, l2, l3);
    }
    {
        float v0a = 0.f, v0b = 0.f, v1a = 0.f, v1b = 0.f;
        if (q == 0) {
            v0a = disp[(((size_t)b*3+0)*NS + n1)*Kn + k1];
            v0b = disp[(((size_t)b*3+1)*NS + n1)*Kn + k1];
            v1a = disp[(((size_t)b*3+0)*NS + n2)*Kn + k2];
            v1b = disp[(((size_t)b*3+1)*NS + n2)*Kn + k2];
        } else if (q == 1) {
            v0a = disp[(((size_t)b*3+2)*NS + n1)*Kn + k1];
            v1a = disp[(((size_t)b*3+2)*NS + n2)*Kn + k2];
        }
        uint32_t h0,h1,l0,l1;
        split2(v0a, v0b, h0, l0);
        split2(v1a, v1b, h1, l1);
        uint32_t* d8 = dst0 + (size_t)8*32*8;
        *(uint4*)(d8)     = make_uint4(h0, h1, 0u, 0u);
        *(uint4*)(d8 + 4) = make_uint4(l0, l1, 0u, 0u);
    }
}

// ---------------- P2: fused dual-MLP GEMM -> logits ----------------
__global__ __launch_bounds__(256) void mlp_gemm(
    const float* __restrict__ db1, const float* __restrict__ rb1,
    const float* __restrict__ dw2, const float* __restrict__ rw2)
{
    extern __shared__ uint32_t s_b[];
    const int tid  = threadIdx.x;
    const int lane = tid & 31;
    const int w    = tid >> 5;

    {
        const uint4* src = (const uint4*)g_mfrag;
        uint4* dst = (uint4*)s_b;
        for (int i = tid; i < 5184; i += 256) dst[i] = src[i];
    }
    __syncthreads();

    int t = blockIdx.x*8 + w;
    if (t >= NTILE) return;

    float c[18][4];
#pragma unroll
    for (int nf = 0; nf < 18; nf++)
#pragma unroll
        for (int j = 0; j < 4; j++) c[nf][j] = 0.f;

    const uint4* af = (const uint4*)g_ffrag;
#pragma unroll 1
    for (int chunk = 0; chunk < 9; chunk++) {
        size_t ai = (((size_t)t*9 + chunk)*32 + lane)*2;
        uint4 ahv = af[ai];
        uint4 alv = af[ai + 1];
        uint32_t ah[4] = {ahv.x, ahv.y, ahv.z, ahv.w};
        uint32_t al[4] = {alv.x, alv.y, alv.z, alv.w};
#pragma unroll
        for (int nf = 0; nf < 18; nf++) {
            uint4 bb = *(const uint4*)&s_b[((chunk*18 + nf)*32 + lane)*4];
            mma_bf16(c[nf], ah, bb.x, bb.y);
            mma_bf16(c[nf], ah, bb.z, bb.w);
            mma_bf16(c[nf], al, bb.x, bb.y);
        }
    }

    float sd1 = 0.f, sd2 = 0.f, sr1 = 0.f, sr2 = 0.f;
    int ocq = (lane & 3)*2;
#pragma unroll
    for (int nf = 0; nf < 18; nf++) {
        int jj = (nf < 9) ? (nf*8 + ocq) : ((nf-9)*8 + ocq);
        const float* B1 = (nf < 9) ? db1 : rb1;
        const float* W2 = (nf < 9) ? dw2 : rw2;
        float bb0 = (jj   < Dhh) ? B1[jj]   : 0.f;
        float bb1 = (jj+1 < Dhh) ? B1[jj+1] : 0.f;
        float w20 = (jj   < Dhh) ? W2[jj]   : 0.f;
        float w21 = (jj+1 < Dhh) ? W2[jj+1] : 0.f;
        float h0 = c[nf][0] + bb0; h0 = (h0 > 0.f) ? h0 : 0.2f*h0;
        float h1 = c[nf][1] + bb1; h1 = (h1 > 0.f) ? h1 : 0.2f*h1;
        float h2 = c[nf][2] + bb0; h2 = (h2 > 0.f) ? h2 : 0.2f*h2;
        float h3 = c[nf][3] + bb1; h3 = (h3 > 0.f) ? h3 : 0.2f*h3;
        float s1 = h0*w20 + h1*w21;
        float s2 = h2*w20 + h3*w21;
        if (nf < 9) { sd1 += s1; sd2 += s2; }
        else        { sr1 += s1; sr2 += s2; }
    }
#pragma unroll
    for (int d = 1; d <= 2; d <<= 1) {
        sd1 += __shfl_xor_sync(0xffffffffu, sd1, d);
        sd2 += __shfl_xor_sync(0xffffffffu, sd2, d);
        sr1 += __shfl_xor_sync(0xffffffffu, sr1, d);
        sr2 += __shfl_xor_sync(0xffffffffu, sr2, d);
    }
    if ((lane & 3) == 0) {
        size_t row = (size_t)t*16 + (lane >> 2);
        g_logd[row]     = sd1;
        g_logd[row + 8] = sd2;
        g_logr[row]     = sr1;
        g_logr[row + 8] = sr2;
    }
}

// ---------------- P3: softmax + weighted neighbor sum ----------------
__global__ __launch_bounds__(64) void point_softmax(
    const int* __restrict__ nbrs,
    const float* __restrict__ d_bias, const float* __restrict__ r_bias)
{
    const int n = blockIdx.x;
    const int b = blockIdx.y;
    const int tid = threadIdx.x;
    __shared__ int s_nb[9];
    if (tid < Kn) s_nb[tid] = nbrs[((size_t)b*NS + n)*Kn + tid];
    __syncthreads();

    size_t base = ((size_t)b*NS + n)*Kn;
    float ld[9], lr[9];
    float mxd = -1e30f, mxr = -1e30f;
#pragma unroll
    for (int k = 0; k < Kn; k++) {
        ld[k] = g_logd[base + k];
        lr[k] = g_logr[base + k];
        mxd = fmaxf(mxd, ld[k]);
        mxr = fmaxf(mxr, lr[k]);
    }
    float sd = 0.f, sr = 0.f;
#pragma unroll
    for (int k = 0; k < Kn; k++) {
        ld[k] = expf(ld[k] - mxd); sd += ld[k];
        lr[k] = expf(lr[k] - mxr); sr += lr[k];
    }
    float invd = 1.f/sd, invr = 1.f/sr;
#pragma unroll
    for (int k = 0; k < Kn; k++) { ld[k] *= invd; lr[k] *= invr; }

    const float* d0b = g_d0 + (size_t)b*HWs*64;
    int ch = tid;
    float ad = d_bias[ch], ar = r_bias[ch];
#pragma unroll
    for (int k = 0; k < Kn; k++) {
        float dn = d0b[(size_t)s_nb[k]*64 + ch];
        ad = fmaf(ld[k], dn, ad);
        ar = fmaf(lr[k], dn, ar);
    }
    g_dfeat[((size_t)b*Cch + ch)*NS + n] = ad;
    g_rfeat[((size_t)b*Cch + ch)*NS + n] = ar;
}

// ---------------- scatter: update NHWC fp32 AND packed tensors 2/3 --------
__global__ __launch_bounds__(128) void scatter_kernel(const int* __restrict__ pc)
{
    const int n = blockIdx.x;
    const int b = blockIdx.y;
    const int tid = threadIdx.x;
    const int idx = pc[(size_t)b*NS + n];
    __shared__ float sd[64], sr[64];

    if (tid < 64) {
        int ch = tid;
        float v = g_dfeat[((size_t)b*Cch + ch)*NS + n];
        size_t o = ((size_t)b*HWs + idx)*64 + ch;
        float nv = (ch == 0) ? v : (g_d0[o] + v);
        g_d0[o] = nv;
        sd[ch] = nv;
    } else {
        int ch = tid - 64;
        float v = g_rfeat[((size_t)b*Cch + ch)*NS + n];
        size_t o = ((size_t)b*HWs + idx)*64 + ch;
        float nv = (ch == 0) ? v : (g_r0[o] + v);
        g_r0[o] = nv;
        sr[ch] = nv;
    }
    __syncthreads();

    // repack updated pixel into packed tensors 2 (d) / 3 (r)
    int set  = tid >> 6;
    int q    = tid & 63;
    int pr   = q >> 1;        // channel pair 0..31
    int part = q & 1;         // 0 = hi, 1 = lo
    int ch   = 2*pr;
    const float* s = set ? sr : sd;
    uint32_t hh, ll;
    split2(s[ch], s[ch+1], hh, ll);
    int cc = ch >> 4;
    size_t off = (((size_t)cc*Bsz + b)*HWs + idx)*16 + (ch & 15);
    if (part == 0)
        *(uint32_t*)&g_pk_h[(size_t)(2+set)*PKT + off] = hh;
    else
        *(uint32_t*)&g_pk_l[(size_t)(2+set)*PKT + off] = ll;
}

// ---------------------------------------------------------------------------
extern "C" void kernel_launch(void* const* d_in, const int* in_sizes, int n_in,
                              void* d_out, int out_size)
{
    const float* rgb    = (const float*)d_in[0];
    const float* sdepth = (const float*)d_in[1];
    const int*   pc     = (const int*)  d_in[2];
    const int*   nbrs   = (const int*)  d_in[3];
    const float* disp   = (const float*)d_in[4];
    const float* d_c0w  = (const float*)d_in[5];
    const float* d_c0b  = (const float*)d_in[6];
    const float* d_c1w  = (const float*)d_in[7];
    const float* d_c1b  = (const float*)d_in[8];
    const float* d_c2w  = (const float*)d_in[9];
    const float* d_c2b  = (const float*)d_in[10];
    const float* r_c0w  = (const float*)d_in[11];
    const float* r_c0b  = (const float*)d_in[12];
    const float* r_c1w  = (const float*)d_in[13];
    const float* r_c1b  = (const float*)d_in[14];
    const float* r_c2w  = (const float*)d_in[15];
    const float* r_c2b  = (const float*)d_in[16];
    const float* d_w1   = (const float*)d_in[17];
    const float* d_b1   = (const float*)d_in[18];
    const float* d_w2   = (const float*)d_in[19];
    const float* d_b2   = (const float*)d_in[20];
    const float* r_w1   = (const float*)d_in[21];
    const float* r_b1   = (const float*)d_in[22];
    const float* r_w2   = (const float*)d_in[23];
    const float* r_b2   = (const float*)d_in[24];
    const float* d_bias = (const float*)d_in[25];
    const float* r_bias = (const float*)d_in[26];
    float* out = (float*)d_out;
    (void)d_b2; (void)r_b2;   // softmax is shift-invariant

    cudaFuncSetAttribute(conv3x3_mma,
                         cudaFuncAttributeMaxDynamicSharedMemorySize, SMEM_CONV);
    cudaFuncSetAttribute(mlp_gemm,
                         cudaFuncAttributeMaxDynamicSharedMemorySize, 82944);

    // weight prepacks: conv sets 0:d0 1:r0 2:d2 3:d1 4:r2 5:r1
    prepack_w<<<dim3(288, 6), 32>>>(d_c0w, r_c0w, d_c2w, d_c1w, r_c2w, r_c1w);
    prepack_mlp<<<162, 32>>>(d_w1, r_w1);
    prepack_src<<<dim3(HWs/64, 2*Bsz), 256>>>(sdepth, rgb);

    dim3 cgrid(Ww/TC, Hh/TR, 2*Bsz);

    // Stage A -> NHWC fp32 + packed tensors 2/3
    conv3x3_mma<<<cgrid, 256, SMEM_CONV>>>(d_c0b, r_c0b,
                                           nullptr, nullptr, nullptr, nullptr,
                                           nullptr, 0);

    // Stage B: tensorized point MLP
    build_feat<<<(NTILE*32 + 255)/256, 256>>>(pc, nbrs, disp);
    mlp_gemm<<<(NTILE + 7)/8, 256, 82944>>>(d_b1, r_b1, d_w2, r_w2);
    point_softmax<<<dim3(NS, Bsz), 64>>>(nbrs, d_bias, r_bias);
    scatter_kernel<<<dim3(NS, Bsz), 128>>>(pc);

    // Stage C (fused dual-source, both tensors) -> NCHW out
    conv3x3_mma<<<cgrid, 256, SMEM_CONV>>>(nullptr, nullptr,
                                           d_c2b, d_c1b, r_c2b, r_c1b,
                                           out, 1);
}

// round 16
// speedup vs baseline: 2.1000x; 1.0100x over previous
#include <cuda_runtime.h>
#include <cuda_bf16.h>
#include <math.h>
#include <stdint.h>

#define Bsz 2
#define Cch 64
#define Hh  256
#define Ww  1216
#define HWs (Hh*Ww)          // 311296
#define NS  20000
#define Kn  9
#define Dd  131
#define Dhh 65
#define ICP 16

// conv tile geometry (proven: warp M=16, 8 rows x 16 cols)
#define TR 8
#define TC 16
#define HR (TR+2)            // 10
#define HC (TC+2)            // 18
#define NCELL (HR*HC)        // 180

// per-stage smem buffer: ah 5760 + al 5760 + B 36864 = 48384
#define BUFB 48384
#define SMEM_CONV (2*BUFB)   // 96768

// packed activation tensor: [cc(4)][b(2)][HW][16ch] bf16
#define PKT ((size_t)4*Bsz*HWs*16)

// point-MLP tiling
#define NROW ((size_t)Bsz*NS*Kn)   // 360000
#define TPB  11250
#define NTILE (Bsz*TPB)            // 22500

// ---------------- scratch (device globals) ----------------
__device__ float g_d0[(size_t)Bsz*HWs*Cch];    // NHWC fp32
__device__ float g_r0[(size_t)Bsz*HWs*Cch];    // NHWC fp32
__device__ float g_dfeat[(size_t)Bsz*Cch*NS];
__device__ float g_rfeat[(size_t)Bsz*Cch*NS];
__device__ __nv_bfloat16 g_pk_h[4*PKT];        // 0 sdepth, 1 rgb, 2 d0', 3 r0'
__device__ __nv_bfloat16 g_pk_l[4*PKT];
#define WSET_U32 36864
__device__ uint32_t g_wfrag[6*WSET_U32];
// feature A-fragments, coalesced layout: [tile][chunk9][part2][lane32] uint4
__device__ uint32_t g_ffrag[(size_t)NTILE*9*2*32*4];
__device__ uint32_t g_mfrag[162*32*4];
__device__ float g_logd[NROW];
__device__ float g_logr[NROW];

// ---------------- helpers ----------------
#define CP16(dst, src, sz) \
    asm volatile("cp.async.cg.shared.global [%0], [%1], 16, %2;\n" \
                 :: "r"(dst), "l"(src), "r"(sz))
#define CPCOMMIT() asm volatile("cp.async.commit_group;\n")
#define CPWAIT(N)  asm volatile("cp.async.wait_group %0;\n" :: "n"(N))

__device__ __forceinline__ uint32_t pack_bf2(float a, float b) {
    __nv_bfloat162 t;
    t.x = __float2bfloat16(a);
    t.y = __float2bfloat16(b);
    return *reinterpret_cast<uint32_t*>(&t);
}

__device__ __forceinline__ void split2(float x, float y, uint32_t& hi, uint32_t& lo) {
    float hx = __bfloat162float(__float2bfloat16(x));
    float hy = __bfloat162float(__float2bfloat16(y));
    hi = pack_bf2(hx, hy);
    lo = pack_bf2(x - hx, y - hy);
}

__device__ __forceinline__ void mma_bf16(float c[4], const uint32_t a[4],
                                         uint32_t b0, uint32_t b1) {
    asm volatile(
        "mma.sync.aligned.m16n8k16.row.col.f32.bf16.bf16.f32 "
        "{%0,%1,%2,%3}, {%4,%5,%6,%7}, {%8,%9}, {%0,%1,%2,%3};"
        : "+f"(c[0]), "+f"(c[1]), "+f"(c[2]), "+f"(c[3])
        : "r"(a[0]), "r"(a[1]), "r"(a[2]), "r"(a[3]), "r"(b0), "r"(b1));
}

__device__ __forceinline__ void ldsm4(uint32_t a[4], uint32_t addr) {
    asm volatile("ldmatrix.sync.aligned.m8n8.x4.shared.b16 {%0,%1,%2,%3}, [%4];"
                 : "=r"(a[0]), "=r"(a[1]), "=r"(a[2]), "=r"(a[3]) : "r"(addr));
}

// ---------------- conv weight prepack ----------------
__global__ void prepack_w(const float* __restrict__ w0, const float* __restrict__ w1,
                          const float* __restrict__ w2, const float* __restrict__ w3,
                          const float* __restrict__ w4, const float* __restrict__ w5)
{
    const float* w;
    switch (blockIdx.y) {
        case 0: w = w0; break; case 1: w = w1; break; case 2: w = w2; break;
        case 3: w = w3; break; case 4: w = w4; break; default: w = w5; break;
    }
    uint32_t* dst = g_wfrag + blockIdx.y * WSET_U32;

    int cb = blockIdx.x;
    int chunk = cb / 72;
    int rem = cb % 72;
    int tap = rem / 8;
    int nf = rem % 8;
    int lane = threadIdx.x;

    int oc = nf*8 + (lane >> 2);
    int k0 = (lane & 3) * 2;
    int ic = chunk*16 + k0;

    float v00 = w[oc*576 + ic*9 + tap];
    float v01 = w[oc*576 + (ic+1)*9 + tap];
    float v10 = w[oc*576 + (ic+8)*9 + tap];
    float v11 = w[oc*576 + (ic+9)*9 + tap];

    size_t base = ((((size_t)chunk*9 + tap)*8 + nf)*32 + lane)*4;
    uint32_t h0, l0, h1, l1;
    split2(v00, v01, h0, l0);
    split2(v10, v11, h1, l1);
    dst[base + 0] = h0;
    dst[base + 1] = h1;
    dst[base + 2] = l0;
    dst[base + 3] = l1;
}

// ---------------- MLP weight prepack ----------------
__global__ void prepack_mlp(const float* __restrict__ dw1, const float* __restrict__ rw1)
{
    int cb = blockIdx.x;
    int chunk = cb / 18, nf = cb % 18;
    int lane = threadIdx.x;
    int jl = lane >> 2;
    int kq = 2*(lane & 3);
    const float* W;
    int j;
    if (nf < 9) { W = dw1; j = nf*8 + jl; }
    else        { W = rw1; j = (nf-9)*8 + jl; }
    bool jv = (j < Dhh);
    int k0 = chunk*16 + kq;
    float v0 = (jv && k0   < Dd) ? W[(k0  )*Dhh + j] : 0.f;
    float v1 = (jv && k0+1 < Dd) ? W[(k0+1)*Dhh + j] : 0.f;
    float v2 = (jv && k0+8 < Dd) ? W[(k0+8)*Dhh + j] : 0.f;
    float v3 = (jv && k0+9 < Dd) ? W[(k0+9)*Dhh + j] : 0.f;
    uint32_t h0, l0, h1, l1;
    split2(v0, v1, h0, l0);
    split2(v2, v3, h1, l1);
    *(uint4*)&g_mfrag[((size_t)cb*32 + lane)*4] = make_uint4(h0, h1, l0, l1);
}

// ---------------- source prepack: NCHW fp32 -> packed bf16 hi/lo -----------
__global__ __launch_bounds__(256) void prepack_src(
    const float* __restrict__ sdepth, const float* __restrict__ rgb)
{
    __shared__ float s[64][65];
    const int tid = threadIdx.x;
    const int hw0 = blockIdx.x * 64;
    const int set = blockIdx.y & 1;
    const int b   = blockIdx.y >> 1;
    const float* src = set ? rgb : sdepth;
    __nv_bfloat16* dsth = g_pk_h + (size_t)set*PKT;
    __nv_bfloat16* dstl = g_pk_l + (size_t)set*PKT;

    for (int i = tid; i < 64*64; i += 256) {
        int c = i >> 6, p = i & 63;
        s[c][p] = src[((size_t)b*64 + c)*HWs + hw0 + p];
    }
    __syncthreads();

    for (int i = tid; i < 512; i += 256) {
        int p   = i >> 3;
        int cc  = (i >> 1) & 3;
        int sub = i & 1;
        uint32_t ph[4], pl[4];
#pragma unroll
        for (int j = 0; j < 4; j++)
            split2(s[cc*16 + sub*8 + 2*j][p], s[cc*16 + sub*8 + 2*j+1][p], ph[j], pl[j]);
        size_t o = (((size_t)cc*Bsz + b)*HWs + hw0 + p)*16 + sub*8;
        *(uint4*)&dsth[o] = make_uint4(ph[0], ph[1], ph[2], ph[3]);
        *(uint4*)&dstl[o] = make_uint4(pl[0], pl[1], pl[2], pl[3]);
    }
}

// ---------------- conv 3x3 SAME via mma, cp.async double-buffered ----------
__global__ __launch_bounds__(256) void conv3x3_mma(
    const float* __restrict__ bd0, const float* __restrict__ br0,
    const float* __restrict__ bd2, const float* __restrict__ bd1,
    const float* __restrict__ br2, const float* __restrict__ br1,
    float* __restrict__ outp, int mode)
{
    extern __shared__ __align__(16) unsigned char sraw[];

    const int tid  = threadIdx.x;
    const int lane = tid & 31;
    const int wid  = tid >> 5;
    const int w0c  = blockIdx.x * TC;
    const int h0   = blockIdx.y * TR;
    const int set  = blockIdx.z & 1;
    const int b    = blockIdx.z >> 1;

    float c[8][4];
#pragma unroll
    for (int nf = 0; nf < 8; nf++)
#pragma unroll
        for (int j = 0; j < 4; j++) c[nf][j] = 0.f;

    const int mm   = lane & 15;
    const int kofs = (lane >> 4) << 3;
    const int n_chunks = mode ? 8 : 4;

    auto fill = [&](int icc, unsigned char* sb) {
        int srcsel = icc >> 2, cc = icc & 3;
        int t, wset;
        if (mode == 0)       { t = set;     wset = set; }
        else if (srcsel == 0){ t = 2 + set; wset = 2 + 2*set; }
        else                 { t = set;     wset = 3 + 2*set; }
        const __nv_bfloat16* bh = g_pk_h + (size_t)t*PKT + ((size_t)cc*Bsz + b)*HWs*16;
        const __nv_bfloat16* bl = g_pk_l + (size_t)t*PKT + ((size_t)cc*Bsz + b)*HWs*16;
        uint32_t s_ah = (uint32_t)__cvta_generic_to_shared(sb);
        uint32_t s_al = s_ah + 5760;
        uint32_t s_bf = s_ah + 11520;
        for (int j = tid; j < NCELL*4; j += 256) {
            int cell = j >> 2, q = j & 3;
            int r = cell / HC, cl = cell - r*HC;
            int h = h0 - 1 + r, w = w0c - 1 + cl;
            bool ok = ((unsigned)h < (unsigned)Hh) && ((unsigned)w < (unsigned)Ww);
            const __nv_bfloat16* sp = ((q & 2) ? bl : bh)
                + (ok ? (((size_t)h*Ww + w)*16 + (size_t)((q & 1)*8)) : 0);
            uint32_t dp = ((q & 2) ? s_al : s_ah) + cell*32 + (q & 1)*16;
            CP16(dp, sp, ok ? 16 : 0);
        }
        const uint4* wsrc = (const uint4*)(g_wfrag + (size_t)wset*WSET_U32 + (size_t)cc*9216);
        for (int i = tid; i < 2304; i += 256)
            CP16(s_bf + i*16, wsrc + i, 16);
    };

    fill(0, sraw);
    CPCOMMIT();

#pragma unroll 1
    for (int icc = 0; icc < n_chunks; icc++) {
        unsigned char* cur = sraw + (icc & 1)*BUFB;
        if (icc + 1 < n_chunks) {
            fill(icc + 1, sraw + ((icc + 1) & 1)*BUFB);
            CPCOMMIT();
            CPWAIT(1);
        } else {
            CPWAIT(0);
        }
        __syncthreads();

        uint32_t a_hi = (uint32_t)__cvta_generic_to_shared(cur);
        uint32_t a_lo = a_hi + 5760;
        const uint32_t* s_bf = (const uint32_t*)(cur + 11520);
#pragma unroll
        for (int tap = 0; tap < 9; tap++) {
            const int dy = tap / 3, dx = tap % 3;
            uint32_t aidx = (uint32_t)((((wid + dy)*HC) + (mm + dx))*ICP + kofs) * 2u;
            uint32_t ah[4], al[4];
            ldsm4(ah, a_hi + aidx);
            ldsm4(al, a_lo + aidx);
#pragma unroll
            for (int nf = 0; nf < 8; nf++) {
                uint4 bb = *(const uint4*)&s_bf[((tap*8 + nf)*32 + lane)*4];
                mma_bf16(c[nf], ah, bb.x, bb.y);
                mma_bf16(c[nf], ah, bb.z, bb.w);
                mma_bf16(c[nf], al, bb.x, bb.y);
            }
        }
        __syncthreads();
    }

    if (!mode) {
        // NHWC fp32 + packed bf16 (tensors 2/3) epilogue
        float* y = set ? g_r0 : g_d0;
        const float* B = set ? br0 : bd0;
        __nv_bfloat16* th = g_pk_h + (size_t)(2 + set)*PKT;
        __nv_bfloat16* tl = g_pk_l + (size_t)(2 + set)*PKT;
        int col0 = lane >> 2;
        int ocq  = (lane & 3)*2;
        size_t hwb = (size_t)(h0 + wid)*Ww + w0c + col0;
#pragma unroll
        for (int nf = 0; nf < 8; nf++) {
            int oc = nf*8 + ocq;
            float bb0 = B[oc], bb1 = B[oc+1];
            float v00 = fmaxf(c[nf][0] + bb0, 0.f);
            float v01 = fmaxf(c[nf][1] + bb1, 0.f);
            float v10 = fmaxf(c[nf][2] + bb0, 0.f);
            float v11 = fmaxf(c[nf][3] + bb1, 0.f);
            float2 p0 = {v00, v01}, p1 = {v10, v11};
            *(float2*)&y[((size_t)b*HWs + hwb)*64 + oc]     = p0;
            *(float2*)&y[((size_t)b*HWs + hwb + 8)*64 + oc] = p1;
            int cc = nf >> 1;
            int co = (nf & 1)*8 + ocq;
            size_t o0 = (((size_t)cc*Bsz + b)*HWs + hwb)*16 + co;
            uint32_t hh, ll;
            split2(v00, v01, hh, ll);
            *(uint32_t*)&th[o0] = hh;
            *(uint32_t*)&tl[o0] = ll;
            split2(v10, v11, hh, ll);
            *(uint32_t*)&th[o0 + 8*16] = hh;
            *(uint32_t*)&tl[o0 + 8*16] = ll;
        }
    } else {
        // NCHW fp32 epilogue via smem transpose
        float* s_out = (float*)sraw;
        float* y = outp + (size_t)set*Bsz*Cch*HWs;
        {
            int pix0 = wid*16 + (lane >> 2);
            int oc0  = (lane & 3) * 2;
#pragma unroll
            for (int nf = 0; nf < 8; nf++) {
                int oc = nf*8 + oc0;
                s_out[pix0*66 + oc]         = c[nf][0];
                s_out[pix0*66 + oc + 1]     = c[nf][1];
                s_out[(pix0+8)*66 + oc]     = c[nf][2];
                s_out[(pix0+8)*66 + oc + 1] = c[nf][3];
            }
        }
        __syncthreads();
        for (int i = tid; i < 8192; i += 256) {
            int oc = i >> 7;
            int pix = i & 127;
            float bias = set ? (br2[oc] + br1[oc]) : (bd2[oc] + bd1[oc]);
            float v = s_out[pix*66 + oc] + bias;
            v = fmaxf(v, 0.f);
            y[((size_t)(b*Cch + oc))*HWs + (size_t)(h0 + (pix >> 4))*Ww
              + (w0c + (pix & 15))] = v;
        }
    }
}

// ---------------- P1: build feature A-fragments (coalesced layout) ---------
__global__ __launch_bounds__(256) void build_feat(
    const int* __restrict__ pc, const int* __restrict__ nbrs,
    const float* __restrict__ disp)
{
    int gw = (blockIdx.x*256 + threadIdx.x) >> 5;
    if (gw >= NTILE) return;
    int lane = threadIdx.x & 31;
    int b = gw / TPB;
    int row0 = (gw - b*TPB) * 16;
    int q = lane & 3;
    int r1 = lane >> 2;
    int rw1 = row0 + r1, rw2 = rw1 + 8;
    int n1 = rw1/9, k1 = rw1 - n1*9;
    int n2 = rw2/9, k2 = rw2 - n2*9;
    int nb1 = nbrs[((size_t)b*NS + n1)*Kn + k1];
    int nb2 = nbrs[((size_t)b*NS + n2)*Kn + k2];
    int p1 = pc[(size_t)b*NS + n1];
    int p2 = pc[(size_t)b*NS + n2];
    const float* d0b = g_d0 + (size_t)b*HWs*64;
    const float* r0b = g_r0 + (size_t)b*HWs*64;
    uint4* ff = (uint4*)g_ffrag;

#pragma unroll
    for (int dc = 0; dc < 4; dc++) {
        int cA = dc*16 + 2*q, cB = cA + 8;
        float2 nA1 = *(const float2*)&d0b[(size_t)nb1*64 + cA];
        float2 nB1 = *(const float2*)&d0b[(size_t)nb1*64 + cB];
        float2 nA2 = *(const float2*)&d0b[(size_t)nb2*64 + cA];
        float2 nB2 = *(const float2*)&d0b[(size_t)nb2*64 + cB];
        float2 dA1 = *(const float2*)&d0b[(size_t)p1*64 + cA];
        float2 dB1 = *(const float2*)&d0b[(size_t)p1*64 + cB];
        float2 dA2 = *(const float2*)&d0b[(size_t)p2*64 + cA];
        float2 dB2 = *(const float2*)&d0b[(size_t)p2*64 + cB];
        float2 rA1 = *(const float2*)&r0b[(size_t)p1*64 + cA];
        float2 rB1 = *(const float2*)&r0b[(size_t)p1*64 + cB];
        float2 rA2 = *(const float2*)&r0b[(size_t)p2*64 + cA];
        float2 rB2 = *(const float2*)&r0b[(size_t)p2*64 + cB];

        uint32_t h0,h1,h2,h3,l0,l1,l2,l3;
        split2(nA1.x - dA1.x, nA1.y - dA1.y, h0, l0);
        split2(nA2.x - dA2.x, nA2.y - dA2.y, h1, l1);
        split2(nB1.x - dB1.x, nB1.y - dB1.y, h2, l2);
        split2(nB2.x - dB2.x, nB2.y - dB2.y, h3, l3);
        ff[(((size_t)gw*9 + dc)*2 + 0)*32 + lane] = make_uint4(h0, h1, h2, h3);
        ff[(((size_t)gw*9 + dc)*2 + 1)*32 + lane] = make_uint4(l0, l1, l2, l3);
        split2(nA1.x - rA1.x, nA1.y - rA1.y, h0, l0);
        split2(nA2.x - rA2.x, nA2.y - rA2.y, h1, l1);
        split2(nB1.x - rB1.x, nB1.y - rB1.y, h2, l2);
        split2(nB2.x - rB2.x, nB2.y - rB2.y, h3, l3);
        ff[(((size_t)gw*9 + dc + 4)*2 + 0)*32 + lane] = make_uint4(h0, h1, h2, h3);
        ff[(((size_t)gw*9 + dc + 4)*2 + 1)*32 + lane] = make_uint4(l0, l1, l2, l3);
    }
    {
        float v0a = 0.f, v0b = 0.f, v1a = 0.f, v1b = 0.f;
        if (q == 0) {
            v0a = disp[(((size_t)b*3+0)*NS + n1)*Kn + k1];
            v0b = disp[(((size_t)b*3+1)*NS + n1)*Kn + k1];
            v1a = disp[(((size_t)b*3+0)*NS + n2)*Kn + k2];
            v1b = disp[(((size_t)b*3+1)*NS + n2)*Kn + k2];
        } else if (q == 1) {
            v0a = disp[(((size_t)b*3+2)*NS + n1)*Kn + k1];
            v1a = disp[(((size_t)b*3+2)*NS + n2)*Kn + k2];
        }
        uint32_t h0,h1,l0,l1;
        split2(v0a, v0b, h0, l0);
        split2(v1a, v1b, h1, l1);
        ff[(((size_t)gw*9 + 8)*2 + 0)*32 + lane] = make_uint4(h0, h1, 0u, 0u);
        ff[(((size_t)gw*9 + 8)*2 + 1)*32 + lane] = make_uint4(l0, l1, 0u, 0u);
    }
}

// ---------------- P2: fused dual-MLP GEMM -> logits ----------------
__global__ __launch_bounds__(256) void mlp_gemm(
    const float* __restrict__ db1, const float* __restrict__ rb1,
    const float* __restrict__ dw2, const float* __restrict__ rw2)
{
    extern __shared__ uint32_t s_b[];
    const int tid  = threadIdx.x;
    const int lane = tid & 31;
    const int w    = tid >> 5;

    {
        const uint4* src = (const uint4*)g_mfrag;
        uint4* dst = (uint4*)s_b;
        for (int i = tid; i < 5184; i += 256) dst[i] = src[i];
    }
    __syncthreads();

    int t = blockIdx.x*8 + w;
    if (t >= NTILE) return;

    float c[18][4];
#pragma unroll
    for (int nf = 0; nf < 18; nf++)
#pragma unroll
        for (int j = 0; j < 4; j++) c[nf][j] = 0.f;

    const uint4* af = (const uint4*)g_ffrag;
#pragma unroll 1
    for (int chunk = 0; chunk < 9; chunk++) {
        uint4 ahv = af[(((size_t)t*9 + chunk)*2 + 0)*32 + lane];
        uint4 alv = af[(((size_t)t*9 + chunk)*2 + 1)*32 + lane];
        uint32_t ah[4] = {ahv.x, ahv.y, ahv.z, ahv.w};
        uint32_t al[4] = {alv.x, alv.y, alv.z, alv.w};
#pragma unroll
        for (int nf = 0; nf < 18; nf++) {
            uint4 bb = *(const uint4*)&s_b[((chunk*18 + nf)*32 + lane)*4];
            mma_bf16(c[nf], ah, bb.x, bb.y);
            mma_bf16(c[nf], ah, bb.z, bb.w);
            mma_bf16(c[nf], al, bb.x, bb.y);
        }
    }

    float sd1 = 0.f, sd2 = 0.f, sr1 = 0.f, sr2 = 0.f;
    int ocq = (lane & 3)*2;
#pragma unroll
    for (int nf = 0; nf < 18; nf++) {
        int jj = (nf < 9) ? (nf*8 + ocq) : ((nf-9)*8 + ocq);
        const float* B1 = (nf < 9) ? db1 : rb1;
        const float* W2 = (nf < 9) ? dw2 : rw2;
        float bb0 = (jj   < Dhh) ? B1[jj]   : 0.f;
        float bb1 = (jj+1 < Dhh) ? B1[jj+1] : 0.f;
        float w20 = (jj   < Dhh) ? W2[jj]   : 0.f;
        float w21 = (jj+1 < Dhh) ? W2[jj+1] : 0.f;
        float h0 = c[nf][0] + bb0; h0 = (h0 > 0.f) ? h0 : 0.2f*h0;
        float h1 = c[nf][1] + bb1; h1 = (h1 > 0.f) ? h1 : 0.2f*h1;
        float h2 = c[nf][2] + bb0; h2 = (h2 > 0.f) ? h2 : 0.2f*h2;
        float h3 = c[nf][3] + bb1; h3 = (h3 > 0.f) ? h3 : 0.2f*h3;
        float s1 = h0*w20 + h1*w21;
        float s2 = h2*w20 + h3*w21;
        if (nf < 9) { sd1 += s1; sd2 += s2; }
        else        { sr1 += s1; sr2 += s2; }
    }
#pragma unroll
    for (int d = 1; d <= 2; d <<= 1) {
        sd1 += __shfl_xor_sync(0xffffffffu, sd1, d);
        sd2 += __shfl_xor_sync(0xffffffffu, sd2, d);
        sr1 += __shfl_xor_sync(0xffffffffu, sr1, d);
        sr2 += __shfl_xor_sync(0xffffffffu, sr2, d);
    }
    if ((lane & 3) == 0) {
        size_t row = (size_t)t*16 + (lane >> 2);
        g_logd[row]     = sd1;
        g_logd[row + 8] = sd2;
        g_logr[row]     = sr1;
        g_logr[row + 8] = sr2;
    }
}

// ---------------- P3: softmax + weighted neighbor sum ----------------
__global__ __launch_bounds__(64) void point_softmax(
    const int* __restrict__ nbrs,
    const float* __restrict__ d_bias, const float* __restrict__ r_bias)
{
    const int n = blockIdx.x;
    const int b = blockIdx.y;
    const int tid = threadIdx.x;
    __shared__ int s_nb[9];
    if (tid < Kn) s_nb[tid] = nbrs[((size_t)b*NS + n)*Kn + tid];
    __syncthreads();

    size_t base = ((size_t)b*NS + n)*Kn;
    float ld[9], lr[9];
    float mxd = -1e30f, mxr = -1e30f;
#pragma unroll
    for (int k = 0; k < Kn; k++) {
        ld[k] = g_logd[base + k];
        lr[k] = g_logr[base + k];
        mxd = fmaxf(mxd, ld[k]);
        mxr = fmaxf(mxr, lr[k]);
    }
    float sd = 0.f, sr = 0.f;
#pragma unroll
    for (int k = 0; k < Kn; k++) {
        ld[k] = expf(ld[k] - mxd); sd += ld[k];
        lr[k] = expf(lr[k] - mxr); sr += lr[k];
    }
    float invd = 1.f/sd, invr = 1.f/sr;
#pragma unroll
    for (int k = 0; k < Kn; k++) { ld[k] *= invd; lr[k] *= invr; }

    const float* d0b = g_d0 + (size_t)b*HWs*64;
    int ch = tid;
    float ad = d_bias[ch], ar = r_bias[ch];
#pragma unroll
    for (int k = 0; k < Kn; k++) {
        float dn = d0b[(size_t)s_nb[k]*64 + ch];
        ad = fmaf(ld[k], dn, ad);
        ar = fmaf(lr[k], dn, ar);
    }
    g_dfeat[((size_t)b*Cch + ch)*NS + n] = ad;
    g_rfeat[((size_t)b*Cch + ch)*NS + n] = ar;
}

// ---------------- scatter: update NHWC fp32 AND packed tensors 2/3 --------
__global__ __launch_bounds__(128) void scatter_kernel(const int* __restrict__ pc)
{
    const int n = blockIdx.x;
    const int b = blockIdx.y;
    const int tid = threadIdx.x;
    const int idx = pc[(size_t)b*NS + n];
    __shared__ float sd[64], sr[64];

    if (tid < 64) {
        int ch = tid;
        float v = g_dfeat[((size_t)b*Cch + ch)*NS + n];
        size_t o = ((size_t)b*HWs + idx)*64 + ch;
        float nv = (ch == 0) ? v : (g_d0[o] + v);
        g_d0[o] = nv;
        sd[ch] = nv;
    } else {
        int ch = tid - 64;
        float v = g_rfeat[((size_t)b*Cch + ch)*NS + n];
        size_t o = ((size_t)b*HWs + idx)*64 + ch;
        float nv = (ch == 0) ? v : (g_r0[o] + v);
        g_r0[o] = nv;
        sr[ch] = nv;
    }
    __syncthreads();

    int set  = tid >> 6;
    int q    = tid & 63;
    int pr   = q >> 1;
    int part = q & 1;
    int ch   = 2*pr;
    const float* s = set ? sr : sd;
    uint32_t hh, ll;
    split2(s[ch], s[ch+1], hh, ll);
    int cc = ch >> 4;
    size_t off = (((size_t)cc*Bsz + b)*HWs + idx)*16 + (ch & 15);
    if (part == 0)
        *(uint32_t*)&g_pk_h[(size_t)(2+set)*PKT + off] = hh;
    else
        *(uint32_t*)&g_pk_l[(size_t)(2+set)*PKT + off] = ll;
}

// ---------------------------------------------------------------------------
extern "C" void kernel_launch(void* const* d_in, const int* in_sizes, int n_in,
                              void* d_out, int out_size)
{
    const float* rgb    = (const float*)d_in[0];
    const float* sdepth = (const float*)d_in[1];
    const int*   pc     = (const int*)  d_in[2];
    const int*   nbrs   = (const int*)  d_in[3];
    const float* disp   = (const float*)d_in[4];
    const float* d_c0w  = (const float*)d_in[5];
    const float* d_c0b  = (const float*)d_in[6];
    const float* d_c1w  = (const float*)d_in[7];
    const float* d_c1b  = (const float*)d_in[8];
    const float* d_c2w  = (const float*)d_in[9];
    const float* d_c2b  = (const float*)d_in[10];
    const float* r_c0w  = (const float*)d_in[11];
    const float* r_c0b  = (const float*)d_in[12];
    const float* r_c1w  = (const float*)d_in[13];
    const float* r_c1b  = (const float*)d_in[14];
    const float* r_c2w  = (const float*)d_in[15];
    const float* r_c2b  = (const float*)d_in[16];
    const float* d_w1   = (const float*)d_in[17];
    const float* d_b1   = (const float*)d_in[18];
    const float* d_w2   = (const float*)d_in[19];
    const float* d_b2   = (const float*)d_in[20];
    const float* r_w1   = (const float*)d_in[21];
    const float* r_b1   = (const float*)d_in[22];
    const float* r_w2   = (const float*)d_in[23];
    const float* r_b2   = (const float*)d_in[24];
    const float* d_bias = (const float*)d_in[25];
    const float* r_bias = (const float*)d_in[26];
    float* out = (float*)d_out;
    (void)d_b2; (void)r_b2;   // softmax is shift-invariant

    cudaFuncSetAttribute(conv3x3_mma,
                         cudaFuncAttributeMaxDynamicSharedMemorySize, SMEM_CONV);
    cudaFuncSetAttribute(mlp_gemm,
                         cudaFuncAttributeMaxDynamicSharedMemorySize, 82944);

    // weight prepacks: conv sets 0:d0 1:r0 2:d2 3:d1 4:r2 5:r1
    prepack_w<<<dim3(288, 6), 32>>>(d_c0w, r_c0w, d_c2w, d_c1w, r_c2w, r_c1w);
    prepack_mlp<<<162, 32>>>(d_w1, r_w1);
    prepack_src<<<dim3(HWs/64, 2*Bsz), 256>>>(sdepth, rgb);

    dim3 cgrid(Ww/TC, Hh/TR, 2*Bsz);

    // Stage A -> NHWC fp32 + packed tensors 2/3
    conv3x3_mma<<<cgrid, 256, SMEM_CONV>>>(d_c0b, r_c0b,
                                           nullptr, nullptr, nullptr, nullptr,
                                           nullptr, 0);

    // Stage B: tensorized point MLP
    build_feat<<<(NTILE*32 + 255)/256, 256>>>(pc, nbrs, disp);
    mlp_gemm<<<(NTILE + 7)/8, 256, 82944>>>(d_b1, r_b1, d_w2, r_w2);
    point_softmax<<<dim3(NS, Bsz), 64>>>(nbrs, d_bias, r_bias);
    scatter_kernel<<<dim3(NS, Bsz), 128>>>(pc);

    // Stage C (fused dual-source, both tensors) -> NCHW out
    conv3x3_mma<<<cgrid, 256, SMEM_CONV>>>(nullptr, nullptr,
                                           d_c2b, d_c1b, r_c2b, r_c1b,
                                           out, 1);
}